// round 3
// baseline (speedup 1.0000x reference)
#include <cuda_runtime.h>
#include <math.h>

#define BB 128
#define TU 256
#define TBS 128
#define TPS 64
#define HH 512
#define VV 3000
#define VOOVN 3400
#define PTRN 32
#define NEGV (-1e20f)
#define NL (2*VV + TBS)
#define XDIM (4*HH + PTRN)
#define SCORE_SMEM 86016

__device__ __align__(16) float g_W1t[HH*HH];
__device__ __align__(16) float g_W2t[HH*HH];
__device__ __align__(16) float g_Whht[HH*3*HH];
__device__ __align__(16) float g_Wcopyt[HH*HH];
__device__ __align__(16) float g_Wgent[HH*VV];
__device__ __align__(16) float g_Wiht[XDIM*3*HH];
__device__ __align__(16) float g_hW1[BB*HH];
__device__ __align__(16) float g_gh[BB*3*HH];
__device__ __align__(16) float g_gi[BB*3*HH];
__device__ __align__(16) float g_su[BB*TU];
__device__ __align__(16) float g_sb[BB*TBS];
__device__ __align__(16) float g_sp[BB*TPS];
__device__ __align__(16) float g_cpraw[BB*TBS];
__device__ __align__(16) float g_cu[BB*HH];
__device__ __align__(16) float g_cb[BB*HH];
__device__ __align__(16) float g_cpv[BB*HH];
__device__ __align__(16) float g_x[BB*XDIM];
__device__ __align__(16) float g_hnew[BB*HH];
__device__ __align__(16) float g_gen[BB*VV];

__device__ __forceinline__ float tanh_fast(float x){
    float y; asm("tanh.approx.f32 %0, %1;" : "=f"(y) : "f"(x)); return y;
}

// out[c*R + r] = in[r*S + O + c]
__global__ void k_transpose(const float* __restrict__ in, float* __restrict__ out,
                            int R, int C, int S, int O){
    __shared__ float tile[32][33];
    int c0 = blockIdx.x*32, r0 = blockIdx.y*32;
    for (int i = threadIdx.y; i < 32; i += 8){
        int r = r0+i, c = c0+threadIdx.x;
        tile[i][threadIdx.x] = (r < R && c < C) ? in[(size_t)r*S + O + c] : 0.f;
    }
    __syncthreads();
    for (int i = threadIdx.y; i < 32; i += 8){
        int c = c0+i, r = r0+threadIdx.x;
        if (r < R && c < C) out[(size_t)c*R + r] = tile[threadIdx.x][i];
    }
}

// C[128 x N] = A[128 x K] @ Wt[K x N] + bias ; Wt k-major
__global__ void k_gemm128(const float* __restrict__ A, int K, int lda,
                          const float* __restrict__ Wt, int N,
                          const float* __restrict__ bias,
                          float* __restrict__ C, int ldc){
    __shared__ float sA[128*32];
    __shared__ float sW[32*32];
    const int nb = blockIdx.x*32, tid = threadIdx.x;
    const int rg = (tid>>3)*4, cg = (tid&7)*4;
    float acc[4][4] = {};
    for (int kc = 0; kc < K; kc += 32){
        __syncthreads();
        for (int i = tid; i < 1024; i += 256){
            int r = i>>3, c4 = i&7;
            ((float4*)sA)[i] = *(const float4*)(A + (size_t)r*lda + kc + c4*4);
        }
        for (int i = tid; i < 1024; i += 256){
            int r = i>>5, c = i&31, n = nb+c;
            sW[i] = (n < N) ? Wt[(size_t)(kc+r)*N + n] : 0.f;
        }
        __syncthreads();
        #pragma unroll
        for (int kk = 0; kk < 32; kk++){
            float a0=sA[(rg+0)*32+kk], a1=sA[(rg+1)*32+kk], a2=sA[(rg+2)*32+kk], a3=sA[(rg+3)*32+kk];
            float w0=sW[kk*32+cg+0], w1=sW[kk*32+cg+1], w2=sW[kk*32+cg+2], w3=sW[kk*32+cg+3];
            acc[0][0]+=a0*w0; acc[0][1]+=a0*w1; acc[0][2]+=a0*w2; acc[0][3]+=a0*w3;
            acc[1][0]+=a1*w0; acc[1][1]+=a1*w1; acc[1][2]+=a1*w2; acc[1][3]+=a1*w3;
            acc[2][0]+=a2*w0; acc[2][1]+=a2*w1; acc[2][2]+=a2*w2; acc[2][3]+=a2*w3;
            acc[3][0]+=a3*w0; acc[3][1]+=a3*w1; acc[3][2]+=a3*w2; acc[3][3]+=a3*w3;
        }
    }
    #pragma unroll
    for (int i = 0; i < 4; i++)
        #pragma unroll
        for (int j = 0; j < 4; j++){
            int n = nb+cg+j;
            if (n < N) C[(size_t)(rg+i)*ldc + n] = acc[i][j] + (bias ? bias[n] : 0.f);
        }
}

// out[b][t] = sum_n wv[n] * tanh((enc[b,t,:] @ Wt)[n] + av[n])
__global__ void k_score(const float* __restrict__ enc, int T,
                        const float* __restrict__ Wt,
                        const float* __restrict__ addv, int addv_per_b,
                        const float* __restrict__ wv, int wv_per_b,
                        float* __restrict__ out){
    extern __shared__ float smem[];
    float* sEnc = smem;            // 32 x 512
    float* sW   = smem + 16384;    // 32 x 128
    float* sAv  = smem + 20480;    // 512
    float* sWv  = smem + 20992;    // 512
    const int b = blockIdx.y, t0 = blockIdx.x*32, tid = threadIdx.x;
    {
        const float4* src = (const float4*)(enc + ((size_t)(b*T + t0))*HH);
        float4* dst = (float4*)sEnc;
        for (int i = tid; i < 32*128; i += 256) dst[i] = src[i];
    }
    {
        const float* ap = addv + (addv_per_b ? b*HH : 0);
        const float* wp = wv   + (wv_per_b   ? b*HH : 0);
        for (int i = tid; i < HH; i += 256){ sAv[i] = ap[i]; sWv[i] = wp[i]; }
    }
    __syncthreads();
    const int nlane = (tid&31)*4, tg = (tid>>5)*4;
    float sp0=0.f, sp1=0.f, sp2=0.f, sp3=0.f;
    for (int nc = 0; nc < 4; nc++){
        float acc[4][4] = {};
        for (int kc = 0; kc < 16; kc++){
            __syncthreads();
            for (int i = tid; i < 1024; i += 256){
                int row = i>>5, c4 = i&31;
                ((float4*)sW)[i] = *(const float4*)(Wt + (size_t)(kc*32+row)*HH + nc*128 + c4*4);
            }
            __syncthreads();
            #pragma unroll
            for (int kk = 0; kk < 32; kk++){
                const float4 w = *(const float4*)&sW[kk*128 + nlane];
                const float* ep = &sEnc[tg*HH + kc*32 + kk];
                float a0=ep[0], a1=ep[HH], a2=ep[2*HH], a3=ep[3*HH];
                acc[0][0]+=a0*w.x; acc[0][1]+=a0*w.y; acc[0][2]+=a0*w.z; acc[0][3]+=a0*w.w;
                acc[1][0]+=a1*w.x; acc[1][1]+=a1*w.y; acc[1][2]+=a1*w.z; acc[1][3]+=a1*w.w;
                acc[2][0]+=a2*w.x; acc[2][1]+=a2*w.y; acc[2][2]+=a2*w.z; acc[2][3]+=a2*w.w;
                acc[3][0]+=a3*w.x; acc[3][1]+=a3*w.y; acc[3][2]+=a3*w.z; acc[3][3]+=a3*w.w;
            }
        }
        const int nb2 = nc*128 + nlane;
        float w0=sWv[nb2+0], w1=sWv[nb2+1], w2=sWv[nb2+2], w3=sWv[nb2+3];
        float v0=sAv[nb2+0], v1=sAv[nb2+1], v2=sAv[nb2+2], v3=sAv[nb2+3];
        sp0 += w0*tanh_fast(acc[0][0]+v0)+w1*tanh_fast(acc[0][1]+v1)+w2*tanh_fast(acc[0][2]+v2)+w3*tanh_fast(acc[0][3]+v3);
        sp1 += w0*tanh_fast(acc[1][0]+v0)+w1*tanh_fast(acc[1][1]+v1)+w2*tanh_fast(acc[1][2]+v2)+w3*tanh_fast(acc[1][3]+v3);
        sp2 += w0*tanh_fast(acc[2][0]+v0)+w1*tanh_fast(acc[2][1]+v1)+w2*tanh_fast(acc[2][2]+v2)+w3*tanh_fast(acc[2][3]+v3);
        sp3 += w0*tanh_fast(acc[3][0]+v0)+w1*tanh_fast(acc[3][1]+v1)+w2*tanh_fast(acc[3][2]+v2)+w3*tanh_fast(acc[3][3]+v3);
    }
    #pragma unroll
    for (int off = 16; off; off >>= 1){
        sp0 += __shfl_xor_sync(0xffffffffu, sp0, off);
        sp1 += __shfl_xor_sync(0xffffffffu, sp1, off);
        sp2 += __shfl_xor_sync(0xffffffffu, sp2, off);
        sp3 += __shfl_xor_sync(0xffffffffu, sp3, off);
    }
    if ((tid&31) == 0){
        out[b*T + t0 + tg + 0] = sp0;
        out[b*T + t0 + tg + 1] = sp1;
        out[b*T + t0 + tg + 2] = sp2;
        out[b*T + t0 + tg + 3] = sp3;
    }
}

// masked softmax over T + ctx = a @ enc
__global__ void k_ctx(const float* __restrict__ enc, const int* __restrict__ ids,
                      const float* __restrict__ scores, int T, float* __restrict__ ctx){
    const int b = blockIdx.x, tid = threadIdx.x;
    __shared__ float sP[256];
    __shared__ float sRed[256];
    __shared__ float sInv;
    float p = 0.f;
    if (tid < T) p = (ids[b*T + tid] == 0) ? 0.f : expf(scores[b*T + tid]);
    sP[tid] = p; sRed[tid] = p;
    __syncthreads();
    for (int s = 128; s; s >>= 1){ if (tid < s) sRed[tid] += sRed[tid+s]; __syncthreads(); }
    if (tid == 0) sInv = 1.f / sRed[0];
    __syncthreads();
    const float inv = sInv;
    for (int h = tid; h < HH; h += 256){
        float acc = 0.f;
        #pragma unroll 4
        for (int t = 0; t < T; t++) acc += sP[t] * enc[((size_t)(b*T + t))*HH + h];
        ctx[b*HH + h] = acc * inv;
    }
}

__global__ void k_build_x(const int* __restrict__ w, const float* __restrict__ emb,
                          const float* __restrict__ cu, const float* __restrict__ cb,
                          const float* __restrict__ cp, const float* __restrict__ db,
                          float* __restrict__ x){
    int i = blockIdx.x*256 + threadIdx.x;
    if (i >= BB*XDIM) return;
    int b = i / XDIM, c = i % XDIM;
    float v;
    if      (c < 512)  v = emb[(size_t)w[b]*HH + c];
    else if (c < 1024) v = cu[b*HH + c - 512];
    else if (c < 1536) v = cb[b*HH + c - 1024];
    else if (c < 2048) v = cp[b*HH + c - 1536];
    else               v = db[b*PTRN + c - 2048];
    x[i] = v;
}

__global__ void k_gru(const float* __restrict__ gi, const float* __restrict__ gh,
                      const float* __restrict__ h0, float* __restrict__ hnew){
    int i = blockIdx.x*256 + threadIdx.x;
    if (i >= BB*HH) return;
    int b = i / HH, n = i % HH;
    const float* gib = gi + (size_t)b*3*HH;
    const float* ghb = gh + (size_t)b*3*HH;
    float r  = 1.f/(1.f + expf(-(gib[n] + ghb[n])));
    float z  = 1.f/(1.f + expf(-(gib[HH+n] + ghb[HH+n])));
    float nn = tanhf(gib[2*HH+n] + r*ghb[2*HH+n]);
    hnew[i]  = (1.f - z)*nn + z*h0[i];
}

__global__ void k_final(const float* __restrict__ gen, const float* __restrict__ cpraw,
                        const int* __restrict__ bids, const int* __restrict__ nounk,
                        float* __restrict__ out){
    const int b = blockIdx.x, tid = threadIdx.x;
    __shared__ float sCps[VV + TBS];
    __shared__ float sAdd[VOOVN - VV];
    __shared__ float sRed[256];
    __shared__ float sZ;
    for (int i = tid; i < VV + TBS; i += 256) sCps[i] = 0.f;
    for (int i = tid; i < VOOVN - VV; i += 256) sAdd[i] = 0.f;
    __syncthreads();
    if (tid == 0){  // deterministic scatter-add (replaces bspn_onehot einsum)
        for (int t = 0; t < TBS; t++){
            float cr = cpraw[b*TBS + t];
            if (bids[b*TBS + t] == 0) cr = NEGV;
            int nk = nounk[b*TBS + t];
            int col = (nk < VV) ? nk : (VV + t);
            sCps[col] += cr;
        }
    }
    __syncthreads();
    float m = -INFINITY;
    for (int i = tid; i < NL; i += 256){
        float v = (i < VV) ? gen[(size_t)b*VV + i] : sCps[i - VV];
        m = fmaxf(m, v);
    }
    sRed[tid] = m; __syncthreads();
    for (int s = 128; s; s >>= 1){ if (tid < s) sRed[tid] = fmaxf(sRed[tid], sRed[tid+s]); __syncthreads(); }
    m = sRed[0]; __syncthreads();
    float sum = 0.f;
    for (int i = tid; i < NL; i += 256){
        float v = (i < VV) ? gen[(size_t)b*VV + i] : sCps[i - VV];
        sum += expf(v - m);
    }
    sRed[tid] = sum; __syncthreads();
    for (int s = 128; s; s >>= 1){ if (tid < s) sRed[tid] += sRed[tid+s]; __syncthreads(); }
    if (tid == 0) sZ = m + logf(sRed[0]);
    __syncthreads();
    const float Z = sZ;
    for (int v = tid; v < VV; v += 256){
        float a = gen[(size_t)b*VV + v] - Z;
        float c = sCps[v] - Z;
        float hi = fmaxf(a, c), lo = fminf(a, c);
        out[(size_t)b*VOOVN + v] = hi + log1pf(expf(lo - hi));
    }
    __syncthreads();
    if (tid == 0){  // deterministic VOOV scatter
        for (int t = 0; t < TBS; t++){
            int nk = nounk[b*TBS + t];
            if (nk >= VV) sAdd[nk - VV] += expf(sCps[VV + t] - Z);
        }
    }
    __syncthreads();
    for (int j = tid; j < VOOVN - VV; j += 256){
        float a = sAdd[j];
        out[(size_t)b*VOOVN + VV + j] = (a > 0.f) ? logf(fmaxf(a, 1e-38f)) : NEGV;
    }
}

extern "C" void kernel_launch(void* const* d_in, const int* in_sizes, int n_in,
                              void* d_out, int out_size){
    (void)in_sizes; (void)n_in; (void)out_size;
    const int*   dec_last_w = (const int*)  d_in[0];
    const float* h0         = (const float*)d_in[1];
    const float* usdx_h     = (const float*)d_in[2];
    const float* bspn_h     = (const float*)d_in[3];
    const float* pvaspn_h   = (const float*)d_in[4];
    const float* db         = (const float*)d_in[5];
    const int*   usdx_ids   = (const int*)  d_in[6];
    const int*   bspn_ids   = (const int*)  d_in[7];
    const int*   pvaspn_ids = (const int*)  d_in[8];
    const int*   bspn_nounk = (const int*)  d_in[9];
    /* d_in[10] bspn_onehot: unused */
    const float* emb_table  = (const float*)d_in[11];
    const float* attn_W     = (const float*)d_in[12];
    const float* attn_b     = (const float*)d_in[13];
    const float* v_w        = (const float*)d_in[14];
    const float* Wcopy_w    = (const float*)d_in[15];
    const float* Wcopy_b    = (const float*)d_in[16];
    const float* Wgen_w     = (const float*)d_in[17];
    const float* Wgen_b     = (const float*)d_in[18];
    const float* gru_W_ih   = (const float*)d_in[19];
    const float* gru_W_hh   = (const float*)d_in[20];
    const float* gru_b_ih   = (const float*)d_in[21];
    const float* gru_b_hh   = (const float*)d_in[22];
    float* out = (float*)d_out;

    float *W1t,*W2t,*Whht,*Wcopyt,*Wgent,*Wiht,*hW1,*gh,*gi,*su,*sb,*spv,*cpraw,*cu,*cb,*cpv,*x,*hnew,*gen;
    cudaGetSymbolAddress((void**)&W1t, g_W1t);
    cudaGetSymbolAddress((void**)&W2t, g_W2t);
    cudaGetSymbolAddress((void**)&Whht, g_Whht);
    cudaGetSymbolAddress((void**)&Wcopyt, g_Wcopyt);
    cudaGetSymbolAddress((void**)&Wgent, g_Wgent);
    cudaGetSymbolAddress((void**)&Wiht, g_Wiht);
    cudaGetSymbolAddress((void**)&hW1, g_hW1);
    cudaGetSymbolAddress((void**)&gh, g_gh);
    cudaGetSymbolAddress((void**)&gi, g_gi);
    cudaGetSymbolAddress((void**)&su, g_su);
    cudaGetSymbolAddress((void**)&sb, g_sb);
    cudaGetSymbolAddress((void**)&spv, g_sp);
    cudaGetSymbolAddress((void**)&cpraw, g_cpraw);
    cudaGetSymbolAddress((void**)&cu, g_cu);
    cudaGetSymbolAddress((void**)&cb, g_cb);
    cudaGetSymbolAddress((void**)&cpv, g_cpv);
    cudaGetSymbolAddress((void**)&x, g_x);
    cudaGetSymbolAddress((void**)&hnew, g_hnew);
    cudaGetSymbolAddress((void**)&gen, g_gen);

    cudaFuncSetAttribute(k_score, cudaFuncAttributeMaxDynamicSharedMemorySize, SCORE_SMEM);

    dim3 tb(32, 8);
    k_transpose<<<dim3(16,16), tb>>>(attn_W,   W1t,    512,  512, 1024, 0);
    k_transpose<<<dim3(16,16), tb>>>(attn_W,   W2t,    512,  512, 1024, 512);
    k_transpose<<<dim3(16,48), tb>>>(gru_W_hh, Whht,  1536,  512,  512, 0);
    k_transpose<<<dim3(16,16), tb>>>(Wcopy_w,  Wcopyt, 512,  512,  512, 0);
    k_transpose<<<dim3(16,94), tb>>>(Wgen_w,   Wgent, 3000,  512,  512, 0);
    k_transpose<<<dim3(65,48), tb>>>(gru_W_ih, Wiht,  1536, 2080, 2080, 0);

    k_gemm128<<<16, 256>>>(h0, 512, 512, W1t, 512, attn_b, hW1, 512);
    k_gemm128<<<48, 256>>>(h0, 512, 512, Whht, 1536, gru_b_hh, gh, 1536);

    k_score<<<dim3(8, BB), 256, SCORE_SMEM>>>(usdx_h,   TU,  W2t, hW1, 1, v_w, 0, su);
    k_score<<<dim3(4, BB), 256, SCORE_SMEM>>>(bspn_h,   TBS, W2t, hW1, 1, v_w, 0, sb);
    k_score<<<dim3(2, BB), 256, SCORE_SMEM>>>(pvaspn_h, TPS, W2t, hW1, 1, v_w, 0, spv);

    k_ctx<<<BB, 256>>>(usdx_h,   usdx_ids,   su,  TU,  cu);
    k_ctx<<<BB, 256>>>(bspn_h,   bspn_ids,   sb,  TBS, cb);
    k_ctx<<<BB, 256>>>(pvaspn_h, pvaspn_ids, spv, TPS, cpv);

    k_build_x<<<(BB*XDIM + 255)/256, 256>>>(dec_last_w, emb_table, cu, cb, cpv, db, x);
    k_gemm128<<<48, 256>>>(x, XDIM, XDIM, Wiht, 1536, gru_b_ih, gi, 1536);
    k_gru<<<(BB*HH + 255)/256, 256>>>(gi, gh, h0, hnew);

    k_gemm128<<<94, 256>>>(hnew, 512, 512, Wgent, 3000, Wgen_b, gen, 3000);
    k_score<<<dim3(4, BB), 256, SCORE_SMEM>>>(bspn_h, TBS, Wcopyt, Wcopy_b, 0, hnew, 1, cpraw);

    k_final<<<BB, 256>>>(gen, cpraw, bspn_ids, bspn_nounk, out);
}

// round 5
// speedup vs baseline: 1.7887x; 1.7887x over previous
#include <cuda_runtime.h>
#include <cuda_bf16.h>
#include <math.h>

#define BB 128
#define TU 256
#define TBS 128
#define TPS 64
#define HH 512
#define VV 3000
#define VOOVN 3400
#define PTRN 32
#define NEGV (-1e20f)
#define NL (2*VV + TBS)
#define XDIM (4*HH + PTRN)

#define SA_LD 520
#define SB_LD 72
#define MMA_SMEM (128*SA_LD*2 + 64*SB_LD*2 + 2*512*4)   /* 146432 */

// ---------------- fp32 scratch ----------------
__device__ __align__(16) float g_W1t[HH*HH];
__device__ __align__(16) float g_Whht[HH*3*HH];
__device__ __align__(16) float g_Wiht[XDIM*3*HH];
__device__ __align__(16) float g_hW1[BB*HH];
__device__ __align__(16) float g_gh[BB*3*HH];
__device__ __align__(16) float g_gi[BB*3*HH];
__device__ __align__(16) float g_su[BB*TU];
__device__ __align__(16) float g_sb[BB*TBS];
__device__ __align__(16) float g_sp[BB*TPS];
__device__ __align__(16) float g_cpraw[BB*TBS];
__device__ __align__(16) float g_cu[BB*HH];
__device__ __align__(16) float g_cb[BB*HH];
__device__ __align__(16) float g_cpv[BB*HH];
__device__ __align__(16) float g_x[BB*XDIM];
__device__ __align__(16) float g_hnew[BB*HH];
__device__ __align__(16) float g_gen[BB*VV];
// ---------------- bf16 scratch ----------------
__device__ __align__(16) __nv_bfloat16 g_usdxb[BB*TU*HH];
__device__ __align__(16) __nv_bfloat16 g_bspnb[BB*TBS*HH];
__device__ __align__(16) __nv_bfloat16 g_pvb[BB*TPS*HH];
__device__ __align__(16) __nv_bfloat16 g_Wab[HH*HH];
__device__ __align__(16) __nv_bfloat16 g_Wcb[HH*HH];
__device__ __align__(16) __nv_bfloat16 g_Wgb[VV*HH];
__device__ __align__(16) __nv_bfloat16 g_hnewb[BB*HH];

__device__ __forceinline__ float tanh_fast(float x){
    float y; asm("tanh.approx.f32 %0, %1;" : "=f"(y) : "f"(x)); return y;
}

// ---------------- fp32 -> bf16 converters ----------------
__global__ void k_f2b(const float* __restrict__ in, __nv_bfloat16* __restrict__ out, int n4){
    int i = blockIdx.x*256 + threadIdx.x;
    if (i >= n4) return;
    float4 v = ((const float4*)in)[i];
    __nv_bfloat162 lo = __floats2bfloat162_rn(v.x, v.y);
    __nv_bfloat162 hi = __floats2bfloat162_rn(v.z, v.w);
    ((__nv_bfloat162*)out)[2*i]   = lo;
    ((__nv_bfloat162*)out)[2*i+1] = hi;
}
// out[r*cols + c] = in[r*stride + off + c], vector-4 over cols
__global__ void k_f2b_stride(const float* __restrict__ in, __nv_bfloat16* __restrict__ out,
                             int rows, int cols, int stride, int off){
    int i = blockIdx.x*256 + threadIdx.x;
    int tot = rows*cols/4;
    if (i >= tot) return;
    int r = (i*4)/cols, c = (i*4)%cols;
    float4 v = *(const float4*)(in + (size_t)r*stride + off + c);
    __nv_bfloat162 lo = __floats2bfloat162_rn(v.x, v.y);
    __nv_bfloat162 hi = __floats2bfloat162_rn(v.z, v.w);
    *(__nv_bfloat162*)(out + (size_t)r*cols + c)     = lo;
    *(__nv_bfloat162*)(out + (size_t)r*cols + c + 2) = hi;
}

// ---------------- transpose ----------------
__global__ void k_transpose(const float* __restrict__ in, float* __restrict__ out,
                            int R, int C, int S, int O){
    __shared__ float tile[32][33];
    int c0 = blockIdx.x*32, r0 = blockIdx.y*32;
    for (int i = threadIdx.y; i < 32; i += 8){
        int r = r0+i, c = c0+threadIdx.x;
        tile[i][threadIdx.x] = (r < R && c < C) ? in[(size_t)r*S + O + c] : 0.f;
    }
    __syncthreads();
    for (int i = threadIdx.y; i < 32; i += 8){
        int c = c0+i, r = r0+threadIdx.x;
        if (r < R && c < C) out[(size_t)c*R + r] = tile[threadIdx.x][i];
    }
}

// ---------------- fp32 GEMM (small uses: hW1, gh, gi) ----------------
__global__ void k_gemm128(const float* __restrict__ A, int K, int lda,
                          const float* __restrict__ Wt, int N,
                          const float* __restrict__ bias,
                          float* __restrict__ C, int ldc){
    __shared__ float sA[128*32];
    __shared__ float sW[32*32];
    const int nb = blockIdx.x*32, tid = threadIdx.x;
    const int rg = (tid>>3)*4, cg = (tid&7)*4;
    float acc[4][4] = {};
    for (int kc = 0; kc < K; kc += 32){
        __syncthreads();
        for (int i = tid; i < 1024; i += 256){
            int r = i>>3, c4 = i&7;
            ((float4*)sA)[i] = *(const float4*)(A + (size_t)r*lda + kc + c4*4);
        }
        for (int i = tid; i < 1024; i += 256){
            int r = i>>5, c = i&31, n = nb+c;
            sW[i] = (n < N) ? Wt[(size_t)(kc+r)*N + n] : 0.f;
        }
        __syncthreads();
        #pragma unroll
        for (int kk = 0; kk < 32; kk++){
            float a0=sA[(rg+0)*32+kk], a1=sA[(rg+1)*32+kk], a2=sA[(rg+2)*32+kk], a3=sA[(rg+3)*32+kk];
            float w0=sW[kk*32+cg+0], w1=sW[kk*32+cg+1], w2=sW[kk*32+cg+2], w3=sW[kk*32+cg+3];
            acc[0][0]+=a0*w0; acc[0][1]+=a0*w1; acc[0][2]+=a0*w2; acc[0][3]+=a0*w3;
            acc[1][0]+=a1*w0; acc[1][1]+=a1*w1; acc[1][2]+=a1*w2; acc[1][3]+=a1*w3;
            acc[2][0]+=a2*w0; acc[2][1]+=a2*w1; acc[2][2]+=a2*w2; acc[2][3]+=a2*w3;
            acc[3][0]+=a3*w0; acc[3][1]+=a3*w1; acc[3][2]+=a3*w2; acc[3][3]+=a3*w3;
        }
    }
    #pragma unroll
    for (int i = 0; i < 4; i++)
        #pragma unroll
        for (int j = 0; j < 4; j++){
            int n = nb+cg+j;
            if (n < N) C[(size_t)(rg+i)*ldc + n] = acc[i][j] + (bias ? bias[n] : 0.f);
        }
}

// ---------------- bf16 tensor-core GEMM, K=512 fixed -----------------------
// mode 0 (score): out[b*T+t] = sum_n wv[n]*tanh(acc[t][n] + av[n]); N must be 512
// mode 1 (plain): out[t*ldc+n] = acc[t][n] + bias[n]
// A: enc bf16 [B*T x 512] row-major.  Wb: bf16 [N x 512] row-major (= B col-major).
// grid: (n-superblocks, B, ceil(T/128)); block: 128 threads.
__global__ void k_mma(const __nv_bfloat16* __restrict__ enc, int T,
                      const __nv_bfloat16* __restrict__ Wb, int N,
                      const float* __restrict__ av, int av_per_b,
                      const float* __restrict__ wv, int wv_per_b,
                      const float* __restrict__ bias,
                      float* __restrict__ out, int ldc, int mode, int nc_per_blk){
    extern __shared__ char smraw[];
    __nv_bfloat16* sA = (__nv_bfloat16*)smraw;                        // 128 x 520
    __nv_bfloat16* sB = (__nv_bfloat16*)(smraw + 128*SA_LD*2);        // 64 x 72
    float* sAv = (float*)(smraw + 128*SA_LD*2 + 64*SB_LD*2);
    float* sWv = sAv + 512;

    const int b = blockIdx.y;
    const int t0 = blockIdx.z * 128;
    const int tid = threadIdx.x;
    const int warp = tid >> 5, lane = tid & 31;
    const int g = lane >> 2, tig = lane & 3;

    // stage A (zero-fill invalid tokens)
    {
        const uint4* src = (const uint4*)(enc + ((size_t)b*T + t0)*512);
        for (int idx = tid; idx < 8192; idx += 128){
            int m = idx >> 6, c8 = idx & 63;
            uint4 v = make_uint4(0,0,0,0);
            if (t0 + m < T) v = src[(size_t)m*64 + c8];
            *(uint4*)&sA[m*SA_LD + c8*8] = v;
        }
        if (mode == 0){
            const float* ap = av + (av_per_b ? b*512 : 0);
            const float* wp = wv + (wv_per_b ? b*512 : 0);
            for (int i = tid; i < 512; i += 128){ sAv[i] = ap[i]; sWv[i] = wp[i]; }
        }
    }

    float s00 = 0.f, s01 = 0.f, s10 = 0.f, s11 = 0.f;   // [mtile][row-half]

    const int ncEnd = (N + 63) >> 6;
    const int nc0 = blockIdx.x * nc_per_blk;
    for (int nc = nc0; nc < nc0 + nc_per_blk && nc < ncEnd; nc++){
        float acc[2][8][4];
        #pragma unroll
        for (int mt = 0; mt < 2; mt++)
            #pragma unroll
            for (int nt = 0; nt < 8; nt++)
                #pragma unroll
                for (int j = 0; j < 4; j++) acc[mt][nt][j] = 0.f;

        for (int kc = 0; kc < 8; kc++){
            __syncthreads();
            for (int idx = tid; idx < 512; idx += 128){
                int r = idx >> 3, c8 = idx & 7;
                int n = nc*64 + r;
                uint4 v = make_uint4(0,0,0,0);
                if (n < N) v = *(const uint4*)(Wb + (size_t)n*512 + kc*64 + c8*8);
                *(uint4*)&sB[r*SB_LD + c8*8] = v;
            }
            __syncthreads();
            #pragma unroll
            for (int ks = 0; ks < 4; ks++){
                const int k0 = kc*64 + ks*16 + tig*2;
                unsigned a[2][4];
                #pragma unroll
                for (int mt = 0; mt < 2; mt++){
                    int r0 = warp*32 + mt*16 + g;
                    a[mt][0] = *(const unsigned*)&sA[(size_t)r0*SA_LD + k0];
                    a[mt][1] = *(const unsigned*)&sA[(size_t)(r0+8)*SA_LD + k0];
                    a[mt][2] = *(const unsigned*)&sA[(size_t)r0*SA_LD + k0 + 8];
                    a[mt][3] = *(const unsigned*)&sA[(size_t)(r0+8)*SA_LD + k0 + 8];
                }
                #pragma unroll
                for (int nt = 0; nt < 8; nt++){
                    unsigned b0 = *(const unsigned*)&sB[(nt*8+g)*SB_LD + ks*16 + tig*2];
                    unsigned b1 = *(const unsigned*)&sB[(nt*8+g)*SB_LD + ks*16 + tig*2 + 8];
                    #pragma unroll
                    for (int mt = 0; mt < 2; mt++){
                        asm volatile(
                            "mma.sync.aligned.m16n8k16.row.col.f32.bf16.bf16.f32 "
                            "{%0,%1,%2,%3}, {%4,%5,%6,%7}, {%8,%9}, {%0,%1,%2,%3};"
                            : "+f"(acc[mt][nt][0]), "+f"(acc[mt][nt][1]),
                              "+f"(acc[mt][nt][2]), "+f"(acc[mt][nt][3])
                            : "r"(a[mt][0]), "r"(a[mt][1]), "r"(a[mt][2]), "r"(a[mt][3]),
                              "r"(b0), "r"(b1));
                    }
                }
            }
        }
        // epilogue for this 64-wide n chunk
        if (mode == 0){
            #pragma unroll
            for (int nt = 0; nt < 8; nt++){
                int n0 = nc*64 + nt*8 + tig*2;
                float w0 = sWv[n0], w1 = sWv[n0+1];
                float v0 = sAv[n0], v1 = sAv[n0+1];
                s00 += w0*tanh_fast(acc[0][nt][0]+v0) + w1*tanh_fast(acc[0][nt][1]+v1);
                s01 += w0*tanh_fast(acc[0][nt][2]+v0) + w1*tanh_fast(acc[0][nt][3]+v1);
                s10 += w0*tanh_fast(acc[1][nt][0]+v0) + w1*tanh_fast(acc[1][nt][1]+v1);
                s11 += w0*tanh_fast(acc[1][nt][2]+v0) + w1*tanh_fast(acc[1][nt][3]+v1);
            }
        } else {
            #pragma unroll
            for (int nt = 0; nt < 8; nt++){
                int n0 = nc*64 + nt*8 + tig*2;
                #pragma unroll
                for (int mt = 0; mt < 2; mt++){
                    int r0 = warp*32 + mt*16 + g;
                    if (n0 < N){
                        out[(size_t)r0*ldc + n0]     = acc[mt][nt][0] + bias[n0];
                        out[(size_t)(r0+8)*ldc + n0] = acc[mt][nt][2] + bias[n0];
                    }
                    if (n0 + 1 < N){
                        out[(size_t)r0*ldc + n0+1]     = acc[mt][nt][1] + bias[n0+1];
                        out[(size_t)(r0+8)*ldc + n0+1] = acc[mt][nt][3] + bias[n0+1];
                    }
                }
            }
        }
    }

    if (mode == 0){
        s00 += __shfl_xor_sync(0xffffffffu, s00, 1); s00 += __shfl_xor_sync(0xffffffffu, s00, 2);
        s01 += __shfl_xor_sync(0xffffffffu, s01, 1); s01 += __shfl_xor_sync(0xffffffffu, s01, 2);
        s10 += __shfl_xor_sync(0xffffffffu, s10, 1); s10 += __shfl_xor_sync(0xffffffffu, s10, 2);
        s11 += __shfl_xor_sync(0xffffffffu, s11, 1); s11 += __shfl_xor_sync(0xffffffffu, s11, 2);
        if (tig == 0){
            int base = t0 + warp*32;
            int t;
            t = base + g;          if (t < T) out[(size_t)b*T + t] = s00;
            t = base + 8 + g;      if (t < T) out[(size_t)b*T + t] = s01;
            t = base + 16 + g;     if (t < T) out[(size_t)b*T + t] = s10;
            t = base + 24 + g;     if (t < T) out[(size_t)b*T + t] = s11;
        }
    }
}

// ---------------- masked softmax + ctx ----------------
__global__ void k_ctx(const float* __restrict__ enc, const int* __restrict__ ids,
                      const float* __restrict__ scores, int T, float* __restrict__ ctx){
    const int b = blockIdx.x, tid = threadIdx.x;
    __shared__ float sP[256];
    __shared__ float sRed[256];
    __shared__ float sInv;
    float p = 0.f;
    if (tid < T) p = (ids[b*T + tid] == 0) ? 0.f : expf(scores[b*T + tid]);
    sP[tid] = p; sRed[tid] = p;
    __syncthreads();
    for (int s = 128; s; s >>= 1){ if (tid < s) sRed[tid] += sRed[tid+s]; __syncthreads(); }
    if (tid == 0) sInv = 1.f / sRed[0];
    __syncthreads();
    const float inv = sInv;
    for (int h = tid; h < HH; h += 256){
        float acc = 0.f;
        #pragma unroll 4
        for (int t = 0; t < T; t++) acc += sP[t] * enc[((size_t)(b*T + t))*HH + h];
        ctx[b*HH + h] = acc * inv;
    }
}

__global__ void k_build_x(const int* __restrict__ w, const float* __restrict__ emb,
                          const float* __restrict__ cu, const float* __restrict__ cb,
                          const float* __restrict__ cp, const float* __restrict__ db,
                          float* __restrict__ x){
    int i = blockIdx.x*256 + threadIdx.x;
    if (i >= BB*XDIM) return;
    int b = i / XDIM, c = i % XDIM;
    float v;
    if      (c < 512)  v = emb[(size_t)w[b]*HH + c];
    else if (c < 1024) v = cu[b*HH + c - 512];
    else if (c < 1536) v = cb[b*HH + c - 1024];
    else if (c < 2048) v = cp[b*HH + c - 1536];
    else               v = db[b*PTRN + c - 2048];
    x[i] = v;
}

__global__ void k_gru(const float* __restrict__ gi, const float* __restrict__ gh,
                      const float* __restrict__ h0, float* __restrict__ hnew,
                      __nv_bfloat16* __restrict__ hnewb){
    int i = blockIdx.x*256 + threadIdx.x;
    if (i >= BB*HH) return;
    int b = i / HH, n = i % HH;
    const float* gib = gi + (size_t)b*3*HH;
    const float* ghb = gh + (size_t)b*3*HH;
    float r  = 1.f/(1.f + expf(-(gib[n] + ghb[n])));
    float z  = 1.f/(1.f + expf(-(gib[HH+n] + ghb[HH+n])));
    float nn = tanhf(gib[2*HH+n] + r*ghb[2*HH+n]);
    float h  = (1.f - z)*nn + z*h0[i];
    hnew[i]  = h;
    hnewb[i] = __float2bfloat16_rn(h);
}

__global__ void k_final(const float* __restrict__ gen, const float* __restrict__ cpraw,
                        const int* __restrict__ bids, const int* __restrict__ nounk,
                        float* __restrict__ out){
    const int b = blockIdx.x, tid = threadIdx.x;
    __shared__ float sCps[VV + TBS];
    __shared__ float sAdd[VOOVN - VV];
    __shared__ float sRed[256];
    __shared__ float sZ;
    for (int i = tid; i < VV + TBS; i += 256) sCps[i] = 0.f;
    for (int i = tid; i < VOOVN - VV; i += 256) sAdd[i] = 0.f;
    __syncthreads();
    if (tid == 0){
        for (int t = 0; t < TBS; t++){
            float cr = cpraw[b*TBS + t];
            if (bids[b*TBS + t] == 0) cr = NEGV;
            int nk = nounk[b*TBS + t];
            int col = (nk < VV) ? nk : (VV + t);
            sCps[col] += cr;
        }
    }
    __syncthreads();
    float m = -INFINITY;
    for (int i = tid; i < NL; i += 256){
        float v = (i < VV) ? gen[(size_t)b*VV + i] : sCps[i - VV];
        m = fmaxf(m, v);
    }
    sRed[tid] = m; __syncthreads();
    for (int s = 128; s; s >>= 1){ if (tid < s) sRed[tid] = fmaxf(sRed[tid], sRed[tid+s]); __syncthreads(); }
    m = sRed[0]; __syncthreads();
    float sum = 0.f;
    for (int i = tid; i < NL; i += 256){
        float v = (i < VV) ? gen[(size_t)b*VV + i] : sCps[i - VV];
        sum += expf(v - m);
    }
    sRed[tid] = sum; __syncthreads();
    for (int s = 128; s; s >>= 1){ if (tid < s) sRed[tid] += sRed[tid+s]; __syncthreads(); }
    if (tid == 0) sZ = m + logf(sRed[0]);
    __syncthreads();
    const float Z = sZ;
    for (int v = tid; v < VV; v += 256){
        float a = gen[(size_t)b*VV + v] - Z;
        float c = sCps[v] - Z;
        float hi = fmaxf(a, c), lo = fminf(a, c);
        out[(size_t)b*VOOVN + v] = hi + log1pf(expf(lo - hi));
    }
    __syncthreads();
    if (tid == 0){
        for (int t = 0; t < TBS; t++){
            int nk = nounk[b*TBS + t];
            if (nk >= VV) sAdd[nk - VV] += expf(sCps[VV + t] - Z);
        }
    }
    __syncthreads();
    for (int j = tid; j < VOOVN - VV; j += 256){
        float a = sAdd[j];
        out[(size_t)b*VOOVN + VV + j] = (a > 0.f) ? logf(fmaxf(a, 1e-38f)) : NEGV;
    }
}

extern "C" void kernel_launch(void* const* d_in, const int* in_sizes, int n_in,
                              void* d_out, int out_size){
    (void)in_sizes; (void)n_in; (void)out_size;
    const int*   dec_last_w = (const int*)  d_in[0];
    const float* h0         = (const float*)d_in[1];
    const float* usdx_h     = (const float*)d_in[2];
    const float* bspn_h     = (const float*)d_in[3];
    const float* pvaspn_h   = (const float*)d_in[4];
    const float* db         = (const float*)d_in[5];
    const int*   usdx_ids   = (const int*)  d_in[6];
    const int*   bspn_ids   = (const int*)  d_in[7];
    const int*   pvaspn_ids = (const int*)  d_in[8];
    const int*   bspn_nounk = (const int*)  d_in[9];
    /* d_in[10] bspn_onehot: unused */
    const float* emb_table  = (const float*)d_in[11];
    const float* attn_W     = (const float*)d_in[12];
    const float* attn_b     = (const float*)d_in[13];
    const float* v_w        = (const float*)d_in[14];
    const float* Wcopy_w    = (const float*)d_in[15];
    const float* Wcopy_b    = (const float*)d_in[16];
    const float* Wgen_w     = (const float*)d_in[17];
    const float* Wgen_b     = (const float*)d_in[18];
    const float* gru_W_ih   = (const float*)d_in[19];
    const float* gru_W_hh   = (const float*)d_in[20];
    const float* gru_b_ih   = (const float*)d_in[21];
    const float* gru_b_hh   = (const float*)d_in[22];
    float* out = (float*)d_out;

    float *W1t,*Whht,*Wiht,*hW1,*gh,*gi,*su,*sb,*spv,*cpraw,*cu,*cb,*cpv,*x,*hnew,*gen;
    __nv_bfloat16 *usdxb,*bspnb,*pvb,*Wab,*Wcb,*Wgb,*hnewb;
    cudaGetSymbolAddress((void**)&W1t, g_W1t);
    cudaGetSymbolAddress((void**)&Whht, g_Whht);
    cudaGetSymbolAddress((void**)&Wiht, g_Wiht);
    cudaGetSymbolAddress((void**)&hW1, g_hW1);
    cudaGetSymbolAddress((void**)&gh, g_gh);
    cudaGetSymbolAddress((void**)&gi, g_gi);
    cudaGetSymbolAddress((void**)&su, g_su);
    cudaGetSymbolAddress((void**)&sb, g_sb);
    cudaGetSymbolAddress((void**)&spv, g_sp);
    cudaGetSymbolAddress((void**)&cpraw, g_cpraw);
    cudaGetSymbolAddress((void**)&cu, g_cu);
    cudaGetSymbolAddress((void**)&cb, g_cb);
    cudaGetSymbolAddress((void**)&cpv, g_cpv);
    cudaGetSymbolAddress((void**)&x, g_x);
    cudaGetSymbolAddress((void**)&hnew, g_hnew);
    cudaGetSymbolAddress((void**)&gen, g_gen);
    cudaGetSymbolAddress((void**)&usdxb, g_usdxb);
    cudaGetSymbolAddress((void**)&bspnb, g_bspnb);
    cudaGetSymbolAddress((void**)&pvb, g_pvb);
    cudaGetSymbolAddress((void**)&Wab, g_Wab);
    cudaGetSymbolAddress((void**)&Wcb, g_Wcb);
    cudaGetSymbolAddress((void**)&Wgb, g_Wgb);
    cudaGetSymbolAddress((void**)&hnewb, g_hnewb);

    cudaFuncSetAttribute(k_mma, cudaFuncAttributeMaxDynamicSharedMemorySize, MMA_SMEM);

    // bf16 conversions (every replay)
    k_f2b<<<(BB*TU*HH/4 + 255)/256, 256>>>(usdx_h,   usdxb, BB*TU*HH/4);
    k_f2b<<<(BB*TBS*HH/4 + 255)/256, 256>>>(bspn_h,  bspnb, BB*TBS*HH/4);
    k_f2b<<<(BB*TPS*HH/4 + 255)/256, 256>>>(pvaspn_h,pvb,   BB*TPS*HH/4);
    k_f2b<<<(HH*HH/4 + 255)/256, 256>>>(Wcopy_w, Wcb, HH*HH/4);
    k_f2b<<<(VV*HH/4 + 255)/256, 256>>>(Wgen_w,  Wgb, VV*HH/4);
    k_f2b_stride<<<(HH*HH/4 + 255)/256, 256>>>(attn_W, Wab, HH, HH, 2*HH, HH);

    // fp32 weight transposes for the small GEMMs
    dim3 tb(32, 8);
    k_transpose<<<dim3(16,16), tb>>>(attn_W,   W1t,   512,  512, 1024, 0);
    k_transpose<<<dim3(16,48), tb>>>(gru_W_hh, Whht, 1536,  512,  512, 0);
    k_transpose<<<dim3(65,48), tb>>>(gru_W_ih, Wiht, 1536, 2080, 2080, 0);

    k_gemm128<<<16, 256>>>(h0, 512, 512, W1t,  512,  attn_b,   hW1, 512);
    k_gemm128<<<48, 256>>>(h0, 512, 512, Whht, 1536, gru_b_hh, gh,  1536);

    // tensor-core fused attention scores
    k_mma<<<dim3(1,BB,2), 128, MMA_SMEM>>>(usdxb, TU,  Wab, 512, hW1, 1, v_w, 0, nullptr, su,  0, 0, 8);
    k_mma<<<dim3(1,BB,1), 128, MMA_SMEM>>>(bspnb, TBS, Wab, 512, hW1, 1, v_w, 0, nullptr, sb,  0, 0, 8);
    k_mma<<<dim3(1,BB,1), 128, MMA_SMEM>>>(pvb,   TPS, Wab, 512, hW1, 1, v_w, 0, nullptr, spv, 0, 0, 8);

    k_ctx<<<BB, 256>>>(usdx_h,   usdx_ids,   su,  TU,  cu);
    k_ctx<<<BB, 256>>>(bspn_h,   bspn_ids,   sb,  TBS, cb);
    k_ctx<<<BB, 256>>>(pvaspn_h, pvaspn_ids, spv, TPS, cpv);

    k_build_x<<<(BB*XDIM + 255)/256, 256>>>(dec_last_w, emb_table, cu, cb, cpv, db, x);
    k_gemm128<<<48, 256>>>(x, XDIM, XDIM, Wiht, 1536, gru_b_ih, gi, 1536);
    k_gru<<<(BB*HH + 255)/256, 256>>>(gi, gh, h0, hnew, hnewb);

    // tensor-core gen logits (47 blocks, one 64-col chunk each) + copy scores
    k_mma<<<dim3(47,1,1), 128, MMA_SMEM>>>(hnewb, 128, Wgb, VV, nullptr, 0, nullptr, 0, Wgen_b, gen, VV, 1, 1);
    k_mma<<<dim3(1,BB,1), 128, MMA_SMEM>>>(bspnb, TBS, Wcb, 512, Wcopy_b, 0, hnew, 1, nullptr, cpraw, 0, 0, 8);

    k_final<<<BB, 256>>>(gen, cpraw, bspn_ids, bspn_nounk, out);
}